// round 17
// baseline (speedup 1.0000x reference)
#include <cuda_runtime.h>
#include <cstdint>

// FHE BSGS rotate/mul/accumulate. Fixed shapes: x[64,65536] f32, diag[16,65536] f32,
// stride=1, reps=1 -> out[b,s] = sum_t x[b,(s2+2^t)&65535] * diag[t,s2], s2 = s^32768.
// R17 = R16 (BPC=4, tile 256, union 768, far-tap rotation, dv pipeline) with the
// near-union staging switched from 12 per-thread LDGSTS to per-batch TMA bulk
// copies (cp.async.bulk -> UBLKCP) against an mbarrier: zero LSU issue cost.
#define SLOTS 65536
#define SQ    (SLOTS / 4)     // 16384 quads per row
#define QM    (SQ - 1)
#define BATCH 64
#define BPC   4               // batches per CTA (all staged at once)
#define TPB   256             // 1 output quad per thread -> 256-quad tile
#define NEARQ 768             // near union: 256 tile + 512 reach (taps t<=11)
#define DATA_BYTES (BPC * NEARQ * 16)         // 49152
#define SMEM_BYTES (DATA_BYTES + 16)          // + mbarrier slot

typedef unsigned long long u64;

__device__ __forceinline__ u64 fma2(u64 x, u64 d, u64 a) {
    u64 r; asm("fma.rn.f32x2 %0, %1, %2, %3;" : "=l"(r) : "l"(x), "l"(d), "l"(a)); return r;
}
__device__ __forceinline__ u64 pack2(float lo, float hi) {
    u64 r; asm("mov.b64 %0, {%1, %2};" : "=l"(r) : "f"(lo), "f"(hi)); return r;
}

__device__ __forceinline__ void bulk_cp(uint32_t saddr, const void* g, uint32_t bytes,
                                        uint32_t mbar) {
    asm volatile(
        "cp.async.bulk.shared::cta.global.mbarrier::complete_tx::bytes [%0], [%1], %2, [%3];"
        :: "r"(saddr), "l"(g), "r"(bytes), "r"(mbar) : "memory");
}

__global__ __launch_bounds__(TPB, 3)
void fhe_bsgs_r17(const float* __restrict__ x,
                  const float* __restrict__ diag,
                  float* __restrict__ out)
{
    extern __shared__ float4 sx[];   // [BPC][NEARQ] data, then mbarrier

    const int tid = threadIdx.x;
    const int Sq  = blockIdx.x * TPB + tid;     // output quad
    const int Tq  = (blockIdx.x * TPB) ^ 8192;  // tile base in s2 space (256-aligned)
    const int q2  = Tq + tid;                   // rolled quad for this thread
    const int b0  = blockIdx.y * BPC;

    const ulonglong2* x8 = reinterpret_cast<const ulonglong2*>(x);
    const float4*     d4 = reinterpret_cast<const float4*>(diag);
    const ulonglong2* d8 = reinterpret_cast<const ulonglong2*>(diag);

    const uint32_t sb0  = (uint32_t)__cvta_generic_to_shared(sx);
    const uint32_t mbar = sb0 + DATA_BYTES;

    // ---- mbarrier init, then one elected thread issues the TMA bulk copies ----
    if (tid == 0) {
        asm volatile("mbarrier.init.shared.b64 [%0], 1;" :: "r"(mbar) : "memory");
    }
    __syncthreads();

    if (tid == 0) {
        asm volatile("mbarrier.arrive.expect_tx.shared.b64 _, [%0], %1;"
                     :: "r"(mbar), "r"((uint32_t)DATA_BYTES) : "memory");
        const int rem = SQ - Tq;                 // quads before ring wrap (>=256)
        #pragma unroll
        for (int b = 0; b < BPC; b++) {
            const char* xb = (const char*)(x + (size_t)(b0 + b) * SLOTS);
            const uint32_t sdst = sb0 + (uint32_t)(b * NEARQ) * 16;
            if (rem >= NEARQ) {
                bulk_cp(sdst, xb + (size_t)Tq * 16, NEARQ * 16, mbar);
            } else {
                bulk_cp(sdst, xb + (size_t)Tq * 16, rem * 16, mbar);
                bulk_cp(sdst + rem * 16, xb, (NEARQ - rem) * 16, mbar);
            }
        }
    }

    // ---- Under the fill: dv loads only (small, coalesced, L2-resident) ----
    const float4 dvs0 = d4[0 * SQ + q2];
    const float4 dvs1 = d4[1 * SQ + q2];
    const float4 dvs2 = d4[2 * SQ + q2];
    ulonglong2 dvA = d8[3 * SQ + q2];      // dv pipeline for near taps
    ulonglong2 dvB = d8[4 * SQ + q2];

    // ---- Wait for TMA completion (acquire; HW-sleep) ----
    {
        uint32_t done;
        asm volatile(
            "{\n\t.reg .pred p;\n\t"
            "mbarrier.try_wait.parity.acquire.cta.shared::cta.b64 p, [%1], 0;\n\t"
            "selp.b32 %0, 1, 0, p;\n\t}"
            : "=r"(done) : "r"(mbar) : "memory");
        if (!done) {
            asm volatile(
                "{\n\t.reg .pred P1;\n\t"
                "WAIT_LOOP_%=:\n\t"
                "mbarrier.try_wait.parity.acquire.cta.shared::cta.b64 P1, [%0], 0, 0x989680;\n\t"
                "@P1 bra.uni WAIT_DONE_%=;\n\t"
                "bra.uni WAIT_LOOP_%=;\n\t"
                "WAIT_DONE_%=:\n\t}"
                :: "r"(mbar) : "memory");
        }
    }

    // Far-tap rotation state: one tap in flight at a time (issued post-fill).
    ulonglong2 dvF = d8[12 * SQ + q2];
    ulonglong2 XF[BPC];
    {
        const unsigned qf = (unsigned)(q2 + 1024) & QM;        // tap 12
        #pragma unroll
        for (int b = 0; b < BPC; b++)
            XF[b] = x8[(size_t)(b0 + b) * SQ + qf];
    }

    u64 accLo[BPC], accHi[BPC];

    // ---- Near t=0..2 (misaligned windows) from smem ----
    #pragma unroll
    for (int b = 0; b < BPC; b++) {
        const float4 A  = sx[b * NEARQ + tid];
        const float4 Bv = sx[b * NEARQ + tid + 1];
        float s0, s1, s2, s3;
        s0 = A.y  * dvs0.x;               // t=0: (A.y,A.z,A.w,B.x)
        s1 = A.z  * dvs0.y;
        s2 = A.w  * dvs0.z;
        s3 = Bv.x * dvs0.w;
        s0 = fmaf(A.z,  dvs1.x, s0);      // t=1: (A.z,A.w,B.x,B.y)
        s1 = fmaf(A.w,  dvs1.y, s1);
        s2 = fmaf(Bv.x, dvs1.z, s2);
        s3 = fmaf(Bv.y, dvs1.w, s3);
        s0 = fmaf(Bv.x, dvs2.x, s0);      // t=2: B
        s1 = fmaf(Bv.y, dvs2.y, s1);
        s2 = fmaf(Bv.z, dvs2.z, s2);
        s3 = fmaf(Bv.w, dvs2.w, s3);
        accLo[b] = pack2(s0, s1);
        accHi[b] = pack2(s2, s3);
    }

    #define NEAR_TAP(T) do {                                            \
        const ulonglong2 dv = dvA;                                      \
        dvA = dvB;                                                      \
        if ((T) + 2 <= 11) dvB = d8[((T) + 2) * SQ + q2];               \
        const int off = tid + (1 << ((T) - 2));                         \
        _Pragma("unroll")                                               \
        for (int b = 0; b < BPC; b++) {                                 \
            const ulonglong2 X =                                        \
                *reinterpret_cast<const ulonglong2*>(&sx[b * NEARQ + off]); \
            accLo[b] = fma2(X.x, dv.x, accLo[b]);                       \
            accHi[b] = fma2(X.y, dv.y, accHi[b]);                       \
        }                                                               \
    } while (0)

    #define FAR_CONSUME_ISSUE(TNEXT) do {                               \
        const ulonglong2 dvc = dvF;                                     \
        ulonglong2 Xc[BPC];                                             \
        _Pragma("unroll")                                               \
        for (int b = 0; b < BPC; b++) Xc[b] = XF[b];                    \
        if ((TNEXT) <= 15) {                                            \
            dvF = d8[(TNEXT) * SQ + q2];                                \
            const unsigned qf = (unsigned)(q2 + (1 << ((TNEXT) - 2))) & QM; \
            _Pragma("unroll")                                           \
            for (int b = 0; b < BPC; b++)                               \
                XF[b] = x8[(size_t)(b0 + b) * SQ + qf];                 \
        }                                                               \
        _Pragma("unroll")                                               \
        for (int b = 0; b < BPC; b++) {                                 \
            accLo[b] = fma2(Xc[b].x, dvc.x, accLo[b]);                  \
            accHi[b] = fma2(Xc[b].y, dvc.y, accHi[b]);                  \
        }                                                               \
    } while (0)

    NEAR_TAP(3);
    NEAR_TAP(4);
    NEAR_TAP(5);
    FAR_CONSUME_ISSUE(13);      // consume tap 12
    NEAR_TAP(6);
    NEAR_TAP(7);
    NEAR_TAP(8);
    FAR_CONSUME_ISSUE(14);      // consume tap 13
    NEAR_TAP(9);
    NEAR_TAP(10);
    FAR_CONSUME_ISSUE(15);      // consume tap 14
    NEAR_TAP(11);
    FAR_CONSUME_ISSUE(16);      // consume tap 15 (no next)

    #undef NEAR_TAP
    #undef FAR_CONSUME_ISSUE

    #pragma unroll
    for (int b = 0; b < BPC; b++)
        reinterpret_cast<ulonglong2*>(out)[(size_t)(b0 + b) * SQ + Sq] =
            make_ulonglong2(accLo[b], accHi[b]);
}

extern "C" void kernel_launch(void* const* d_in, const int* in_sizes, int n_in,
                              void* d_out, int out_size)
{
    const float* x    = (const float*)d_in[0];
    const float* diag = (const float*)d_in[1];
    float* out = (float*)d_out;

    static bool attr_set = false;
    if (!attr_set) {
        cudaFuncSetAttribute(fhe_bsgs_r17,
                             cudaFuncAttributeMaxDynamicSharedMemorySize, SMEM_BYTES);
        attr_set = true;
    }

    dim3 grid(SQ / TPB, BATCH / BPC);   // (64 tiles, 16 batch-groups) = 1024 CTAs
    fhe_bsgs_r17<<<grid, TPB, SMEM_BYTES>>>(x, diag, out);
}